// round 1
// baseline (speedup 1.0000x reference)
#include <cuda_runtime.h>

#define T10 10
#define NT  20
#define NW  3
#define D   128
#define H   8
#define HD  16
#define R   24      // H*NW
#define TPB 128
#define GPB 2       // batches per block

// ---------------- device scratch (precomputed / transposed weights) ----------------
__device__ __align__(16) float g_QWr[R][D];       // [(h*3+w)][e], scaled by 1/sqrt(HD)
__device__ float g_sbias[R];                      // q . bk, scaled
__device__ __align__(16) float g_queries[NW][D];  // LayerNorm'd queries
__device__ __align__(16) float g_wv_t[D][D];      // [e][c]  (c = h*16+d)
__device__ __align__(16) float g_outp_t[D][D];    // [c][o]
__device__ __align__(16) float g_fc1_t[D][2*D];   // [e][j]
__device__ __align__(16) float g_fc2_t[2*D][D];   // [j][o]

// ---------------- transpose weights ----------------
__global__ void transpose_kernel(const float* __restrict__ in_proj_w,
                                 const float* __restrict__ out_proj_w,
                                 const float* __restrict__ fc1_w,
                                 const float* __restrict__ fc2_w)
{
    int idx = blockIdx.x * blockDim.x + threadIdx.x;
    int stride = gridDim.x * blockDim.x;
    for (int i = idx; i < D * D; i += stride) {
        int c = i / D, e = i % D;
        g_wv_t[e][c] = in_proj_w[(2 * D + c) * D + e];
    }
    for (int i = idx; i < D * D; i += stride) {
        int o = i / D, c = i % D;
        g_outp_t[c][o] = out_proj_w[o * D + c];
    }
    for (int i = idx; i < 2 * D * D; i += stride) {
        int j = i / D, e = i % D;
        g_fc1_t[e][j] = fc1_w[j * D + e];
    }
    for (int i = idx; i < 2 * D * D; i += stride) {
        int o = i / (2 * D), j = i % (2 * D);
        g_fc2_t[j][o] = fc2_w[o * 2 * D + j];
    }
}

// ---------------- precompute: query LN, q, QW, score bias ----------------
__global__ void precompute_kernel(const float* __restrict__ query_emb,
                                  const float* __restrict__ qg,
                                  const float* __restrict__ qb,
                                  const float* __restrict__ in_proj_w,
                                  const float* __restrict__ in_proj_b)
{
    __shared__ float sq[NW][D];
    __shared__ float qq[NW][D];
    __shared__ float redA[4], redB[4];
    const int tid = threadIdx.x;
    const int lane = tid & 31, warp = tid >> 5;

    for (int w = 0; w < NW; w++) {
        float v = query_emb[w * D + tid];
        float s = v, s2 = v * v;
        #pragma unroll
        for (int o = 16; o; o >>= 1) {
            s  += __shfl_down_sync(0xffffffffu, s,  o);
            s2 += __shfl_down_sync(0xffffffffu, s2, o);
        }
        if (lane == 0) { redA[warp] = s; redB[warp] = s2; }
        __syncthreads();
        float m  = (redA[0] + redA[1] + redA[2] + redA[3]) * (1.0f / D);
        float vv = (redB[0] + redB[1] + redB[2] + redB[3]) * (1.0f / D) - m * m;
        float rs = rsqrtf(vv + 1e-5f);
        sq[w][tid] = (v - m) * rs * qg[tid] + qb[tid];
        __syncthreads();
    }
    // q = LN(queries) @ wq.T + bq   (wq = in_proj_w[0:D])
    for (int w = 0; w < NW; w++) {
        float acc = in_proj_b[tid];
        for (int e = 0; e < D; e++) acc += sq[w][e] * in_proj_w[tid * D + e];
        qq[w][tid] = acc;
        g_queries[w][tid] = sq[w][tid];
    }
    __syncthreads();
    // QWr[h*3+w][e] = (1/4) sum_d q[w][h*16+d] * wk[h*16+d][e]
    for (int h = 0; h < H; h++)
        for (int w = 0; w < NW; w++) {
            float acc = 0.f;
            #pragma unroll
            for (int d = 0; d < HD; d++)
                acc += qq[w][h * HD + d] * in_proj_w[(D + h * HD + d) * D + tid];
            g_QWr[h * NW + w][tid] = acc * 0.25f;
        }
    if (tid < R) {
        int h = tid / NW, w = tid % NW;
        float acc = 0.f;
        #pragma unroll
        for (int d = 0; d < HD; d++)
            acc += qq[w][h * HD + d] * in_proj_b[D + h * HD + d];
        g_sbias[tid] = acc * 0.25f;
    }
}

// ---------------- fused main kernel ----------------
struct SmemLayout {
    float tok[NT][132];         // padded tokens (one batch at a time)
    float attn[R][NT];          // scores -> attn (one batch at a time)
    float wt[GPB][R][132];      // attention-weighted tokens
    float ctx[GPB][NW][D];
    float x[GPB][NW][D];
    float x2[GPB][NW][D];
    float hbuf[GPB][NW][2 * D];
    float part[4 * 6 * D];      // cross-warp partials; aliased as QW stage [R][D]
    float coords[NT][2];
    float redA[96];
    float redB[96];
};

__device__ __forceinline__ float4 ld4g(const float* p) {
    return *reinterpret_cast<const float4*>(p);
}

__global__ void __launch_bounds__(TPB) fused_kernel(
    const float* __restrict__ track_left,
    const float* __restrict__ track_right,
    const float* __restrict__ coord_w,
    const float* __restrict__ coord_b,
    const float* __restrict__ pos_emb,
    const float* __restrict__ side_emb,
    const float* __restrict__ tok_g,
    const float* __restrict__ tok_b,
    const float* __restrict__ in_proj_b,
    const float* __restrict__ out_proj_b,
    const float* __restrict__ fc1_b,
    const float* __restrict__ fc2_b,
    const float* __restrict__ pa_g, const float* __restrict__ pa_b,
    const float* __restrict__ pf_g, const float* __restrict__ pf_b,
    const float* __restrict__ head_w, const float* __restrict__ head_b,
    float* __restrict__ out)
{
    extern __shared__ float smem_raw[];
    SmemLayout& S = *reinterpret_cast<SmemLayout*>(smem_raw);
    const int tid  = threadIdx.x;
    const int lane = tid & 31;
    const int warp = tid >> 5;

    // stage QW into S.part (acts as [R][D])
    for (int i = tid; i < R * D; i += TPB) S.part[i] = g_QWr[i / D][i % D];

    // hoisted per-feature parameters (thread == feature dim)
    const float cw0 = coord_w[2 * tid], cw1 = coord_w[2 * tid + 1];
    const float cb  = coord_b[tid];
    const float sd0 = side_emb[tid], sd1 = side_emb[D + tid];
    const float tg  = tok_g[tid],  tbv = tok_b[tid];
    float posr[T10];
    #pragma unroll
    for (int t = 0; t < T10; t++) posr[t] = pos_emb[t * D + tid];

    // -------- attention phase, per batch g --------
    for (int g = 0; g < GPB; g++) {
        const int b = blockIdx.x * GPB + g;
        __syncthreads();                 // protect tok/attn/coords reuse
        if (tid < NT) {
            const float* src = (tid < T10)
                ? (track_left  + (b * T10 + tid) * 2)
                : (track_right + (b * T10 + (tid - T10)) * 2);
            S.coords[tid][0] = src[0];
            S.coords[tid][1] = src[1];
        }
        __syncthreads();

        float pre[NT];
        #pragma unroll
        for (int t = 0; t < NT; t++) {
            float base = cb + posr[(t < T10) ? t : (t - T10)] + ((t < T10) ? sd0 : sd1);
            pre[t] = S.coords[t][0] * cw0 + S.coords[t][1] * cw1 + base;
        }
        #pragma unroll
        for (int t = 0; t < NT; t++) {
            float s = pre[t], s2 = pre[t] * pre[t];
            #pragma unroll
            for (int o = 16; o; o >>= 1) {
                s  += __shfl_down_sync(0xffffffffu, s,  o);
                s2 += __shfl_down_sync(0xffffffffu, s2, o);
            }
            if (lane == 0) { S.redA[t * 4 + warp] = s; S.redB[t * 4 + warp] = s2; }
        }
        __syncthreads();
        #pragma unroll
        for (int t = 0; t < NT; t++) {
            float m  = (S.redA[t*4] + S.redA[t*4+1] + S.redA[t*4+2] + S.redA[t*4+3]) * (1.0f / D);
            float vv = (S.redB[t*4] + S.redB[t*4+1] + S.redB[t*4+2] + S.redB[t*4+3]) * (1.0f / D) - m * m;
            float rs = rsqrtf(vv + 1e-5f);
            S.tok[t][tid] = (pre[t] - m) * rs * tg + tbv;
        }
        __syncthreads();

        // scores[r][t] = sbias[r] + QW[r] . tok[t]
        for (int i = tid; i < R * NT; i += TPB) {
            int r = i / NT, t = i % NT;
            float acc = g_sbias[r];
            #pragma unroll 8
            for (int e = 0; e < D; e += 4) {
                float4 q4 = *reinterpret_cast<const float4*>(&S.part[r * D + e]);
                float4 t4 = *reinterpret_cast<const float4*>(&S.tok[t][e]);
                acc += q4.x * t4.x + q4.y * t4.y + q4.z * t4.z + q4.w * t4.w;
            }
            S.attn[r][t] = acc;
        }
        __syncthreads();

        // softmax over t (24 rows)
        if (tid < R) {
            float mx = -1e30f;
            #pragma unroll
            for (int t = 0; t < NT; t++) mx = fmaxf(mx, S.attn[tid][t]);
            float ex[NT], sum = 0.f;
            #pragma unroll
            for (int t = 0; t < NT; t++) { ex[t] = expf(S.attn[tid][t] - mx); sum += ex[t]; }
            float inv = 1.0f / sum;
            #pragma unroll
            for (int t = 0; t < NT; t++) S.attn[tid][t] = ex[t] * inv;
        }
        __syncthreads();

        // wt[r][:] = attn[r] @ tok  — warp handles rows r = warp + 4j, lane -> 4 dims
        {
            float acc[6][4];
            #pragma unroll
            for (int j = 0; j < 6; j++) { acc[j][0]=0.f; acc[j][1]=0.f; acc[j][2]=0.f; acc[j][3]=0.f; }
            #pragma unroll
            for (int t = 0; t < NT; t++) {
                float4 t4 = *reinterpret_cast<const float4*>(&S.tok[t][lane * 4]);
                #pragma unroll
                for (int j = 0; j < 6; j++) {
                    float a = S.attn[warp + 4 * j][t];
                    acc[j][0] += a * t4.x; acc[j][1] += a * t4.y;
                    acc[j][2] += a * t4.z; acc[j][3] += a * t4.w;
                }
            }
            #pragma unroll
            for (int j = 0; j < 6; j++) {
                int r = warp + 4 * j;
                *reinterpret_cast<float4*>(&S.wt[g][r][lane * 4]) =
                    make_float4(acc[j][0], acc[j][1], acc[j][2], acc[j][3]);
            }
        }
    }
    __syncthreads();   // wt complete for both batches

    // -------- ctx = wt @ wv_h.T + bv  (cross-warp partial GEMM) --------
    {
        float acc[GPB][NW][4];
        #pragma unroll
        for (int g2 = 0; g2 < GPB; g2++)
            #pragma unroll
            for (int w = 0; w < NW; w++) { acc[g2][w][0]=0.f; acc[g2][w][1]=0.f; acc[g2][w][2]=0.f; acc[g2][w][3]=0.f; }
        const int h = lane >> 2;      // c = 4*lane .. 4*lane+3 -> head
        const int e0 = warp * 32;
        #pragma unroll 4
        for (int e = e0; e < e0 + 32; e++) {
            float4 w4 = ld4g(&g_wv_t[e][lane * 4]);
            #pragma unroll
            for (int g2 = 0; g2 < GPB; g2++)
                #pragma unroll
                for (int w = 0; w < NW; w++) {
                    float a = S.wt[g2][h * NW + w][e];
                    acc[g2][w][0] += a * w4.x; acc[g2][w][1] += a * w4.y;
                    acc[g2][w][2] += a * w4.z; acc[g2][w][3] += a * w4.w;
                }
        }
        #pragma unroll
        for (int g2 = 0; g2 < GPB; g2++)
            #pragma unroll
            for (int w = 0; w < NW; w++)
                *reinterpret_cast<float4*>(&S.part[(warp * 6 + g2 * NW + w) * D + lane * 4]) =
                    make_float4(acc[g2][w][0], acc[g2][w][1], acc[g2][w][2], acc[g2][w][3]);
        __syncthreads();
        #pragma unroll
        for (int r6 = 0; r6 < 6; r6++) {
            float s = S.part[(0*6+r6)*D+tid] + S.part[(1*6+r6)*D+tid]
                    + S.part[(2*6+r6)*D+tid] + S.part[(3*6+r6)*D+tid];
            S.ctx[r6 / 3][r6 % 3][tid] = s + in_proj_b[2 * D + tid];
        }
        __syncthreads();
    }

    // -------- attn_out = ctx @ out_proj.T + b; x = LN(queries + attn_out) --------
    {
        float acc[GPB][NW][4];
        #pragma unroll
        for (int g2 = 0; g2 < GPB; g2++)
            #pragma unroll
            for (int w = 0; w < NW; w++) { acc[g2][w][0]=0.f; acc[g2][w][1]=0.f; acc[g2][w][2]=0.f; acc[g2][w][3]=0.f; }
        const int c0 = warp * 32;
        #pragma unroll 4
        for (int c = c0; c < c0 + 32; c++) {
            float4 w4 = ld4g(&g_outp_t[c][lane * 4]);
            #pragma unroll
            for (int g2 = 0; g2 < GPB; g2++)
                #pragma unroll
                for (int w = 0; w < NW; w++) {
                    float a = S.ctx[g2][w][c];
                    acc[g2][w][0] += a * w4.x; acc[g2][w][1] += a * w4.y;
                    acc[g2][w][2] += a * w4.z; acc[g2][w][3] += a * w4.w;
                }
        }
        #pragma unroll
        for (int g2 = 0; g2 < GPB; g2++)
            #pragma unroll
            for (int w = 0; w < NW; w++)
                *reinterpret_cast<float4*>(&S.part[(warp * 6 + g2 * NW + w) * D + lane * 4]) =
                    make_float4(acc[g2][w][0], acc[g2][w][1], acc[g2][w][2], acc[g2][w][3]);
        __syncthreads();
        float val[6];
        #pragma unroll
        for (int r6 = 0; r6 < 6; r6++) {
            float s = S.part[(0*6+r6)*D+tid] + S.part[(1*6+r6)*D+tid]
                    + S.part[(2*6+r6)*D+tid] + S.part[(3*6+r6)*D+tid];
            val[r6] = s + out_proj_b[tid] + g_queries[r6 % 3][tid];
        }
        #pragma unroll
        for (int r6 = 0; r6 < 6; r6++) {
            float s = val[r6], s2 = val[r6] * val[r6];
            #pragma unroll
            for (int o = 16; o; o >>= 1) {
                s  += __shfl_down_sync(0xffffffffu, s,  o);
                s2 += __shfl_down_sync(0xffffffffu, s2, o);
            }
            if (lane == 0) { S.redA[r6 * 4 + warp] = s; S.redB[r6 * 4 + warp] = s2; }
        }
        __syncthreads();
        #pragma unroll
        for (int r6 = 0; r6 < 6; r6++) {
            float m  = (S.redA[r6*4] + S.redA[r6*4+1] + S.redA[r6*4+2] + S.redA[r6*4+3]) * (1.0f / D);
            float vv = (S.redB[r6*4] + S.redB[r6*4+1] + S.redB[r6*4+2] + S.redB[r6*4+3]) * (1.0f / D) - m * m;
            float rs = rsqrtf(vv + 1e-5f);
            S.x[r6 / 3][r6 % 3][tid] = (val[r6] - m) * rs * pa_g[tid] + pa_b[tid];
        }
        __syncthreads();
    }

    // -------- fc1 + relu (two halves of 256 outputs) --------
    for (int half = 0; half < 2; half++) {
        float acc[GPB][NW][4];
        #pragma unroll
        for (int g2 = 0; g2 < GPB; g2++)
            #pragma unroll
            for (int w = 0; w < NW; w++) { acc[g2][w][0]=0.f; acc[g2][w][1]=0.f; acc[g2][w][2]=0.f; acc[g2][w][3]=0.f; }
        const int e0 = warp * 32;
        #pragma unroll 4
        for (int e = e0; e < e0 + 32; e++) {
            float4 w4 = ld4g(&g_fc1_t[e][half * D + lane * 4]);
            #pragma unroll
            for (int g2 = 0; g2 < GPB; g2++)
                #pragma unroll
                for (int w = 0; w < NW; w++) {
                    float a = S.x[g2][w][e];
                    acc[g2][w][0] += a * w4.x; acc[g2][w][1] += a * w4.y;
                    acc[g2][w][2] += a * w4.z; acc[g2][w][3] += a * w4.w;
                }
        }
        #pragma unroll
        for (int g2 = 0; g2 < GPB; g2++)
            #pragma unroll
            for (int w = 0; w < NW; w++)
                *reinterpret_cast<float4*>(&S.part[(warp * 6 + g2 * NW + w) * D + lane * 4]) =
                    make_float4(acc[g2][w][0], acc[g2][w][1], acc[g2][w][2], acc[g2][w][3]);
        __syncthreads();
        #pragma unroll
        for (int r6 = 0; r6 < 6; r6++) {
            float s = S.part[(0*6+r6)*D+tid] + S.part[(1*6+r6)*D+tid]
                    + S.part[(2*6+r6)*D+tid] + S.part[(3*6+r6)*D+tid];
            s += fc1_b[half * D + tid];
            S.hbuf[r6 / 3][r6 % 3][half * D + tid] = fmaxf(s, 0.f);
        }
        __syncthreads();
    }

    // -------- fc2 + residual + LN --------
    {
        float acc[GPB][NW][4];
        #pragma unroll
        for (int g2 = 0; g2 < GPB; g2++)
            #pragma unroll
            for (int w = 0; w < NW; w++) { acc[g2][w][0]=0.f; acc[g2][w][1]=0.f; acc[g2][w][2]=0.f; acc[g2][w][3]=0.f; }
        const int j0 = warp * 64;
        #pragma unroll 4
        for (int j = j0; j < j0 + 64; j++) {
            float4 w4 = ld4g(&g_fc2_t[j][lane * 4]);
            #pragma unroll
            for (int g2 = 0; g2 < GPB; g2++)
                #pragma unroll
                for (int w = 0; w < NW; w++) {
                    float a = S.hbuf[g2][w][j];
                    acc[g2][w][0] += a * w4.x; acc[g2][w][1] += a * w4.y;
                    acc[g2][w][2] += a * w4.z; acc[g2][w][3] += a * w4.w;
                }
        }
        #pragma unroll
        for (int g2 = 0; g2 < GPB; g2++)
            #pragma unroll
            for (int w = 0; w < NW; w++)
                *reinterpret_cast<float4*>(&S.part[(warp * 6 + g2 * NW + w) * D + lane * 4]) =
                    make_float4(acc[g2][w][0], acc[g2][w][1], acc[g2][w][2], acc[g2][w][3]);
        __syncthreads();
        float val[6];
        #pragma unroll
        for (int r6 = 0; r6 < 6; r6++) {
            float s = S.part[(0*6+r6)*D+tid] + S.part[(1*6+r6)*D+tid]
                    + S.part[(2*6+r6)*D+tid] + S.part[(3*6+r6)*D+tid];
            val[r6] = s + fc2_b[tid] + S.x[r6 / 3][r6 % 3][tid];
        }
        #pragma unroll
        for (int r6 = 0; r6 < 6; r6++) {
            float s = val[r6], s2 = val[r6] * val[r6];
            #pragma unroll
            for (int o = 16; o; o >>= 1) {
                s  += __shfl_down_sync(0xffffffffu, s,  o);
                s2 += __shfl_down_sync(0xffffffffu, s2, o);
            }
            if (lane == 0) { S.redA[r6 * 4 + warp] = s; S.redB[r6 * 4 + warp] = s2; }
        }
        __syncthreads();
        #pragma unroll
        for (int r6 = 0; r6 < 6; r6++) {
            float m  = (S.redA[r6*4] + S.redA[r6*4+1] + S.redA[r6*4+2] + S.redA[r6*4+3]) * (1.0f / D);
            float vv = (S.redB[r6*4] + S.redB[r6*4+1] + S.redB[r6*4+2] + S.redB[r6*4+3]) * (1.0f / D) - m * m;
            float rs = rsqrtf(vv + 1e-5f);
            S.x2[r6 / 3][r6 % 3][tid] = (val[r6] - m) * rs * pf_g[tid] + pf_b[tid];
        }
        __syncthreads();
    }

    // -------- head: out[b][w][k] = x2[w] . head_w[k] + head_b[k] --------
    {
        const float hw0 = head_w[tid], hw1 = head_w[D + tid];
        #pragma unroll
        for (int r12 = 0; r12 < 12; r12++) {
            int g2 = r12 / 6, rem = r12 % 6, w = rem >> 1, k = rem & 1;
            float v = S.x2[g2][w][tid] * (k ? hw1 : hw0);
            #pragma unroll
            for (int o = 16; o; o >>= 1) v += __shfl_down_sync(0xffffffffu, v, o);
            if (lane == 0) S.redA[r12 * 4 + warp] = v;
        }
        __syncthreads();
        if (tid < 12) {
            int g2 = tid / 6, rem = tid % 6, k = rem & 1;
            float s = S.redA[tid*4] + S.redA[tid*4+1] + S.redA[tid*4+2] + S.redA[tid*4+3] + head_b[k];
            out[(blockIdx.x * GPB + g2) * 6 + rem] = s;
        }
    }
}

// ---------------- launch ----------------
extern "C" void kernel_launch(void* const* d_in, const int* in_sizes, int n_in,
                              void* d_out, int out_size)
{
    const float* track_left   = (const float*)d_in[0];
    const float* track_right  = (const float*)d_in[1];
    const float* coord_w      = (const float*)d_in[2];
    const float* coord_b      = (const float*)d_in[3];
    const float* pos_emb      = (const float*)d_in[4];
    const float* side_emb     = (const float*)d_in[5];
    const float* query_emb    = (const float*)d_in[6];
    const float* tokens_ln_g  = (const float*)d_in[7];
    const float* tokens_ln_b  = (const float*)d_in[8];
    const float* queries_ln_g = (const float*)d_in[9];
    const float* queries_ln_b = (const float*)d_in[10];
    const float* in_proj_w    = (const float*)d_in[11];
    const float* in_proj_b    = (const float*)d_in[12];
    const float* out_proj_w   = (const float*)d_in[13];
    const float* out_proj_b   = (const float*)d_in[14];
    const float* fc1_w        = (const float*)d_in[15];
    const float* fc1_b        = (const float*)d_in[16];
    const float* fc2_w        = (const float*)d_in[17];
    const float* fc2_b        = (const float*)d_in[18];
    const float* pa_g         = (const float*)d_in[19];
    const float* pa_b         = (const float*)d_in[20];
    const float* pf_g         = (const float*)d_in[21];
    const float* pf_b         = (const float*)d_in[22];
    const float* head_w       = (const float*)d_in[23];
    const float* head_b       = (const float*)d_in[24];
    float* out = (float*)d_out;

    const int nb = in_sizes[0] / (T10 * 2);   // number of batches (32768)

    transpose_kernel<<<96, 256>>>(in_proj_w, out_proj_w, fc1_w, fc2_w);
    precompute_kernel<<<1, TPB>>>(query_emb, queries_ln_g, queries_ln_b, in_proj_w, in_proj_b);

    static int smem_set = 0;
    cudaFuncSetAttribute(fused_kernel, cudaFuncAttributeMaxDynamicSharedMemorySize,
                         (int)sizeof(SmemLayout));
    (void)smem_set;

    fused_kernel<<<nb / GPB, TPB, sizeof(SmemLayout)>>>(
        track_left, track_right, coord_w, coord_b, pos_emb, side_emb,
        tokens_ln_g, tokens_ln_b, in_proj_b, out_proj_b, fc1_b, fc2_b,
        pa_g, pa_b, pf_g, pf_b, head_w, head_b, out);
}